// round 3
// baseline (speedup 1.0000x reference)
#include <cuda_runtime.h>
#include <stdint.h>

#define NP   8192
#define KNN  64
#define EPSF 1e-7f

// ------------------------- static scratch -------------------------
__device__ float g_px[NP], g_py[NP], g_pz[NP], g_rr[NP], g_vn[NP];
__device__ float g_axes[12];
__device__ int   g_idx[NP * KNN];
__device__ __align__(16) float g_feat[NP * KNN * 4];
__device__ __align__(16) float g_fd[NP * 4];
__device__ float g_emb[192 * NP];
__device__ float g_y1[64 * NP];
__device__ float g_y2[128 * NP];
__device__ float g_y3[256 * NP];
__device__ float g_y4[1024 * NP];
__device__ float g_sc[1024], g_sh[1024];

// ------------------------- f32x2 helpers -------------------------
__device__ __forceinline__ unsigned long long ffma2(unsigned long long a,
                                                    unsigned long long b,
                                                    unsigned long long c) {
    unsigned long long d;
    asm("fma.rn.f32x2 %0, %1, %2, %3;" : "=l"(d) : "l"(a), "l"(b), "l"(c));
    return d;
}
__device__ __forceinline__ unsigned long long pack2(float x, float y) {
    unsigned long long d;
    asm("mov.b64 %0, {%1, %2};" : "=l"(d) : "f"(x), "f"(y));
    return d;
}
__device__ __forceinline__ void unpack2(unsigned long long v, float& x, float& y) {
    asm("mov.b64 {%0, %1}, %2;" : "=f"(x), "=f"(y) : "l"(v));
}

// ------------------------- prep -------------------------
__global__ void prep_kernel(const float* __restrict__ pts) {
    int i = blockIdx.x * blockDim.x + threadIdx.x;
    if (i < NP) {
        float x = pts[3 * i], y = pts[3 * i + 1], z = pts[3 * i + 2];
        g_px[i] = x; g_py[i] = y; g_pz[i] = z;
        float rr = x * x + y * y + z * z;
        g_rr[i] = rr;
        g_vn[i] = sqrtf(rr);
    }
}

// ------------------------- KNN: rank-64 selection per query -------------------------
__global__ void __launch_bounds__(256) knn_kernel() {
    int i = blockIdx.x, tid = threadIdx.x;
    __shared__ int wsum[8];
    __shared__ int tot_s, cless_s;
    __shared__ unsigned long long cmin;
    __shared__ int nless, neq;
    __shared__ int eqbuf[192];

    float qx = g_px[i], qy = g_py[i], qz = g_pz[i], rq = g_rr[i];

    unsigned key[32];
#pragma unroll
    for (int s = 0; s < 32; s++) {
        int n = s * 256 + tid;
        float d = rq - 2.0f * (qx * g_px[n] + qy * g_py[n] + qz * g_pz[n]) + g_rr[n];
        unsigned u = __float_as_uint(d);
        key[s] = u ^ ((u & 0x80000000u) ? 0xFFFFFFFFu : 0x80000000u);
    }
    if (tid == 0) { cmin = ~0ULL; nless = 0; neq = 0; }

    // bitwise binary search for the rank-63 (0-indexed) key value v
    unsigned v = 0u;
    for (int b = 31; b >= 0; b--) {
        unsigned cand = v | (1u << b);
        int cnt = 0;
#pragma unroll
        for (int s = 0; s < 32; s++) cnt += (key[s] < cand) ? 1 : 0;
        cnt = __reduce_add_sync(0xFFFFFFFFu, cnt);
        if ((tid & 31) == 0) wsum[tid >> 5] = cnt;
        __syncthreads();
        if (tid == 0) { int t = 0; for (int w = 0; w < 8; w++) t += wsum[w]; tot_s = t; }
        __syncthreads();
        if (tot_s < KNN) v = cand;          // uniform across block
    }

    // count strictly-less
    {
        int c2 = 0;
#pragma unroll
        for (int s = 0; s < 32; s++) c2 += (key[s] < v) ? 1 : 0;
        c2 = __reduce_add_sync(0xFFFFFFFFu, c2);
        if ((tid & 31) == 0) wsum[tid >> 5] = c2;
        __syncthreads();
        if (tid == 0) { int t = 0; for (int w = 0; w < 8; w++) t += wsum[w]; cless_s = t; }
    }

    // center = lexicographic min (key, index)  (= rank-0 neighbor, tie lowest idx)
    unsigned long long lm = ~0ULL;
#pragma unroll
    for (int s = 0; s < 32; s++) {
        unsigned long long pk = (((unsigned long long)key[s]) << 32) | (unsigned)(s * 256 + tid);
        lm = (pk < lm) ? pk : lm;
    }
    atomicMin(&cmin, lm);
    __syncthreads();
    int center = (int)(cmin & 0xFFFFFFFFu);
    int cless  = cless_s;

    // gather: strict-less (minus center) into slots 1.., equals buffered
#pragma unroll
    for (int s = 0; s < 32; s++) {
        int n = s * 256 + tid;
        unsigned kk = key[s];
        if (n == center) continue;
        if (kk < v) {
            int p = atomicAdd(&nless, 1);
            g_idx[i * KNN + 1 + p] = n;
        } else if (kk == v) {
            int e = atomicAdd(&neq, 1);
            if (e < 192) eqbuf[e] = n;
        }
    }
    __syncthreads();
    if (tid == 0) {
        g_idx[i * KNN] = center;
        int q = KNN - cless;                 // equals to take, smallest indices first
        int m = neq; if (m > 192) m = 192;
        for (int a = 0; a < q; a++) {
            int bi = a;
            for (int bj = a + 1; bj < m; bj++)
                if (eqbuf[bj] < eqbuf[bi]) bi = bj;
            int t = eqbuf[a]; eqbuf[a] = eqbuf[bi]; eqbuf[bi] = t;
            g_idx[i * KNN + cless + a] = eqbuf[a];
        }
    }
}

// ------------------ per-query rotation-invariant KNN features ------------------
__global__ void __launch_bounds__(64) featknn_kernel() {
    int i = blockIdx.x, k = threadIdx.x;
    __shared__ int sidx[64];
    __shared__ float sx[64], sy[64], sz[64];
    __shared__ unsigned long long sred[64];
    __shared__ float rx[64], ry[64], rz[64];

    sidx[k] = g_idx[i * KNN + k];
    __syncthreads();
    // deterministic order: odd-even sort slots 1..63 by point index (slot 0 = center stays)
    for (int ph = 0; ph < 63; ph++) {
        int a = 1 + (ph & 1) + 2 * k;
        if (a + 1 <= 63) {
            int u = sidx[a], w = sidx[a + 1];
            if (w < u) { sidx[a] = w; sidx[a + 1] = u; }
        }
        __syncthreads();
    }

    int j  = sidx[k];
    int c0 = sidx[0];
    float pcx = g_px[j] - g_px[c0];
    float pcy = g_py[j] - g_py[c0];
    float pcz = g_pz[j] - g_pz[c0];
    float vn  = sqrtf(pcx * pcx + pcy * pcy + pcz * pcz);
    sx[k] = pcx; sy[k] = pcy; sz[k] = pcz;
    rx[k] = pcx; ry[k] = pcy; rz[k] = pcz;
    sred[k] = (((unsigned long long)__float_as_uint(vn)) << 32) | (unsigned)(63 - k);
    __syncthreads();
    for (int off = 32; off > 0; off >>= 1) {
        if (k < off) {
            rx[k] += rx[k + off]; ry[k] += ry[k + off]; rz[k] += rz[k + off];
            unsigned long long o = sred[k + off];
            if (o > sred[k]) sred[k] = o;
        }
        __syncthreads();
    }
    int id1 = 63 - (int)(sred[0] & 0xFFFFFFFFu);
    float a1x = sx[id1], a1y = sy[id1], a1z = sz[id1];
    float n1 = sqrtf(a1x * a1x + a1y * a1y + a1z * a1z) + EPSF;
    a1x /= n1; a1y /= n1; a1z /= n1;
    float a2x = rx[0] * (1.0f / 64.0f), a2y = ry[0] * (1.0f / 64.0f), a2z = rz[0] * (1.0f / 64.0f);
    float n2 = sqrtf(a2x * a2x + a2y * a2y + a2z * a2z) + EPSF;
    a2x /= n2; a2y /= n2; a2z /= n2;
    float a3x = a1x + 1.5f * a2x, a3y = a1y + 1.5f * a2y, a3z = a1z + 1.5f * a2z;
    float n3 = sqrtf(a3x * a3x + a3y * a3y + a3z * a3z) + EPSF;
    a3x /= n3; a3y /= n3; a3z /= n3;

    float den = vn + EPSF;
    float f1 = (pcx * a1x + pcy * a1y + pcz * a1z) / den;
    float f2 = (pcx * a2x + pcy * a2y + pcz * a2z) / den;
    float f3 = (pcx * a3x + pcy * a3y + pcz * a3z) / den;
    float4 o = make_float4(f1, f2, f3, vn);
    *(float4*)(g_feat + (size_t)(i * KNN + k) * 4) = o;
}

// ------------------ global axes (proj_points) ------------------
__global__ void __launch_bounds__(256) axes_kernel() {
    int tid = threadIdx.x;
    __shared__ unsigned long long smax[256], smin[256];
    unsigned long long mx = 0, mn = ~0ULL;
    for (int t = tid; t < NP; t += 256) {
        unsigned b = __float_as_uint(g_vn[t]);   // vn >= 0: uint order == float order
        unsigned long long pmx = (((unsigned long long)b) << 32) | (unsigned)(0xFFFFFFFFu - t);
        unsigned long long pmn = (((unsigned long long)b) << 32) | (unsigned)t;
        if (pmx > mx) mx = pmx;
        if (pmn < mn) mn = pmn;
    }
    smax[tid] = mx; smin[tid] = mn;
    __syncthreads();
    for (int off = 128; off > 0; off >>= 1) {
        if (tid < off) {
            if (smax[tid + off] > smax[tid]) smax[tid] = smax[tid + off];
            if (smin[tid + off] < smin[tid]) smin[tid] = smin[tid + off];
        }
        __syncthreads();
    }
    if (tid == 0) {
        int i1 = (int)(0xFFFFFFFFu - (unsigned)(smax[0] & 0xFFFFFFFFu));
        int i2 = (int)(smin[0] & 0xFFFFFFFFu);
        float n1 = g_vn[i1] + EPSF;
        float a1x = g_px[i1] / n1, a1y = g_py[i1] / n1, a1z = g_pz[i1] / n1;
        float n2 = g_vn[i2] + EPSF;
        float a2x = g_px[i2] / n2, a2y = g_py[i2] / n2, a2z = g_pz[i2] / n2;
        float a3x = a1x + 1.5f * a2x, a3y = a1y + 1.5f * a2y, a3z = a1z + 1.5f * a2z;
        float n3 = sqrtf(a3x * a3x + a3y * a3y + a3z * a3z) + EPSF;
        a3x /= n3; a3y /= n3; a3z /= n3;
        g_axes[0] = a1x; g_axes[1] = a1y; g_axes[2] = a1z;
        g_axes[3] = a2x; g_axes[4] = a2y; g_axes[5] = a2z;
        g_axes[6] = a3x; g_axes[7] = a3y; g_axes[8] = a3z;
    }
}

__global__ void fd_kernel() {
    int i = blockIdx.x * blockDim.x + threadIdx.x;
    if (i < NP) {
        float x = g_px[i], y = g_py[i], z = g_pz[i], vn = g_vn[i];
        float den = vn + EPSF;
        float f1 = (x * g_axes[0] + y * g_axes[1] + z * g_axes[2]) / den;
        float f2 = (x * g_axes[3] + y * g_axes[4] + z * g_axes[5]) / den;
        float f3 = (x * g_axes[6] + y * g_axes[7] + z * g_axes[8]) / den;
        *(float4*)(g_fd + (size_t)i * 4) = make_float4(f1, f2, f3, vn);
    }
}

// ------------------ fused 5-layer MLP + max over K (FFMA2) ------------------
// one point per block, 128 threads; dyn smem: weights 16640 + 2 x 64x66 act
#define MLP_SMEM ((16640 + 2 * 64 * 66) * 4)
__global__ void __launch_bounds__(128) mlp_kernel(const float* __restrict__ gw0,
                                                  const float* __restrict__ gw1,
                                                  const float* __restrict__ gw2,
                                                  const float* __restrict__ gw3,
                                                  const float* __restrict__ gw4) {
    extern __shared__ float smem[];
    float* w = smem;                 // [0..16640)
    float* A = smem + 16640;         // 64 x 66
    float* B = A + 64 * 66;          // 64 x 66
    int tid = threadIdx.x, i = blockIdx.x;

    for (int t = tid; t < 256; t += 128) w[t] = gw0[t];
    {
        const float* gws[4] = {gw1, gw2, gw3, gw4};
        for (int l = 0; l < 4; l++)
            for (int t = tid; t < 4096; t += 128) w[256 + l * 4096 + t] = gws[l][t];
    }
    for (int r = tid; r < 64; r += 128) {
        float4 f = *(const float4*)(g_feat + (size_t)(i * 64 + r) * 4);
        A[r * 66 + 0] = f.x; A[r * 66 + 1] = f.y; A[r * 66 + 2] = f.z; A[r * 66 + 3] = f.w;
    }
    __syncthreads();

    int r = tid >> 1, h = tid & 1;   // row, j-half
    float* cur = A; float* nxt = B;
    const float* wl = w; int Kc = 4;
    for (int layer = 0; layer < 5; layer++) {
        unsigned long long acc[16];
#pragma unroll
        for (int q = 0; q < 16; q++) acc[q] = 0ULL;
        const float* wj = wl + h * 32;
        for (int c = 0; c < Kc; c++) {
            float xv = cur[r * 66 + c];
            unsigned long long xx = pack2(xv, xv);
            const float4* wrow = (const float4*)(wj + c * 64);
#pragma unroll
            for (int q4 = 0; q4 < 8; q4++) {
                float4 wv = wrow[q4];
                unsigned long long b0 = pack2(wv.x, wv.y);
                unsigned long long b1 = pack2(wv.z, wv.w);
                acc[q4 * 2]     = ffma2(xx, b0, acc[q4 * 2]);
                acc[q4 * 2 + 1] = ffma2(xx, b1, acc[q4 * 2 + 1]);
            }
        }
        float* orow = nxt + r * 66 + h * 32;
#pragma unroll
        for (int q = 0; q < 16; q++) {
            float vx, vy; unpack2(acc[q], vx, vy);
            float2 o; o.x = fmaxf(vx, 0.f); o.y = fmaxf(vy, 0.f);
            *(float2*)(orow + q * 2) = o;
        }
        __syncthreads();
        float* t = cur; cur = nxt; nxt = t;
        wl = w + 256 + layer * 4096; Kc = 64;
    }
    if (tid < 64) {
        float m = cur[tid];
        for (int r2 = 1; r2 < 64; r2++) m = fmaxf(m, cur[r2 * 66 + tid]);
        g_emb[i * 64 + tid] = m;     // flat [n][64] == conv view [64][8192]
    }
}

// ------------------ generic GEMM: Y[M][8192] = W[M][Kc] @ X[Kc][8192] + bias ------------------
__global__ void __launch_bounds__(256) gemm_kernel(const float* __restrict__ W,
                                                   const float* __restrict__ X,
                                                   const float* __restrict__ bias,
                                                   float* __restrict__ Y,
                                                   int M, int Kc) {
    __shared__ float sW[16][64];
    __shared__ float sX[16][64];
    int tid = threadIdx.x, tx = tid & 15, ty = tid >> 4;
    int bm = blockIdx.y * 64, bn = blockIdx.x * 64;
    float acc[4][4];
#pragma unroll
    for (int a = 0; a < 4; a++)
#pragma unroll
        for (int b = 0; b < 4; b++) acc[a][b] = 0.f;

    for (int k0 = 0; k0 < Kc; k0 += 16) {
        for (int t2 = tid; t2 < 1024; t2 += 256) {
            int m = t2 & 63, kk = t2 >> 6;
            float v = 0.f;
            if (k0 + kk < Kc) v = W[(bm + m) * Kc + k0 + kk];
            sW[kk][m] = v;
        }
        for (int t2 = tid; t2 < 1024; t2 += 256) {
            int n = t2 & 63, kk = t2 >> 6;
            float v = 0.f;
            if (k0 + kk < Kc) v = X[(k0 + kk) * NP + bn + n];
            sX[kk][n] = v;
        }
        __syncthreads();
#pragma unroll
        for (int kk = 0; kk < 16; kk++) {
            float a[4], b[4];
#pragma unroll
            for (int u = 0; u < 4; u++) { a[u] = sW[kk][ty + u * 16]; b[u] = sX[kk][tx + u * 16]; }
#pragma unroll
            for (int u = 0; u < 4; u++)
#pragma unroll
                for (int vv = 0; vv < 4; vv++) acc[u][vv] += a[u] * b[vv];
        }
        __syncthreads();
    }
#pragma unroll
    for (int u = 0; u < 4; u++) {
        int m = bm + ty + u * 16;
        float bv = bias[m];
#pragma unroll
        for (int vv = 0; vv < 4; vv++)
            Y[(size_t)m * NP + bn + tx + vv * 16] = acc[u][vv] + bv;
    }
}

// ------------------ BatchNorm (training stats) ------------------
__global__ void __launch_bounds__(256) bn_stats_kernel(const float* __restrict__ Y,
                                                       const float* __restrict__ gamma,
                                                       const float* __restrict__ beta) {
    int ch = blockIdx.x, tid = threadIdx.x;
    const float* row = Y + (size_t)ch * NP;
    __shared__ float red[256];
    __shared__ float s_mu;
    float s = 0.f;
    for (int t = tid; t < NP; t += 256) s += row[t];
    red[tid] = s; __syncthreads();
    for (int off = 128; off > 0; off >>= 1) { if (tid < off) red[tid] += red[tid + off]; __syncthreads(); }
    if (tid == 0) s_mu = red[0] * (1.0f / NP);
    __syncthreads();
    float mu = s_mu;
    float s2 = 0.f;
    for (int t = tid; t < NP; t += 256) { float d = row[t] - mu; s2 += d * d; }
    __syncthreads();
    red[tid] = s2; __syncthreads();
    for (int off = 128; off > 0; off >>= 1) { if (tid < off) red[tid] += red[tid + off]; __syncthreads(); }
    if (tid == 0) {
        float var = red[0] * (1.0f / NP);
        float sc = gamma[ch] * rsqrtf(var + 1e-5f);
        g_sc[ch] = sc;
        g_sh[ch] = beta[ch] - mu * sc;
    }
}

__global__ void bn_apply_kernel(const float* __restrict__ Yin, float* __restrict__ Yout) {
    int idx = blockIdx.x * blockDim.x + threadIdx.x;
    int ch = idx >> 13;
    Yout[idx] = fmaxf(Yin[idx] * g_sc[ch] + g_sh[ch], 0.f);
}

// ------------------------- launch -------------------------
extern "C" void kernel_launch(void* const* d_in, const int* in_sizes, int n_in,
                              void* d_out, int out_size) {
    const float* pts  = (const float*)d_in[0];
    const float* gw0  = (const float*)d_in[1];
    const float* gw1  = (const float*)d_in[2];
    const float* gw2  = (const float*)d_in[3];
    const float* gw3  = (const float*)d_in[4];
    const float* gw4  = (const float*)d_in[5];
    const float* c1w  = (const float*)d_in[6];
    const float* c1b  = (const float*)d_in[7];
    const float* bn1g = (const float*)d_in[8];
    const float* bn1b = (const float*)d_in[9];
    const float* c2w  = (const float*)d_in[10];
    const float* c2b  = (const float*)d_in[11];
    const float* bn2g = (const float*)d_in[12];
    const float* bn2b = (const float*)d_in[13];
    const float* c3w  = (const float*)d_in[14];
    const float* c3b  = (const float*)d_in[15];
    const float* bn3g = (const float*)d_in[16];
    const float* bn3b = (const float*)d_in[17];
    const float* c4w  = (const float*)d_in[18];
    const float* c4b  = (const float*)d_in[19];
    const float* bn4g = (const float*)d_in[20];
    const float* bn4b = (const float*)d_in[21];
    float* out = (float*)d_out;

    float *p_fd, *p_emb, *p_y1, *p_y2, *p_y3, *p_y4;
    cudaGetSymbolAddress((void**)&p_fd,  g_fd);
    cudaGetSymbolAddress((void**)&p_emb, g_emb);
    cudaGetSymbolAddress((void**)&p_y1,  g_y1);
    cudaGetSymbolAddress((void**)&p_y2,  g_y2);
    cudaGetSymbolAddress((void**)&p_y3,  g_y3);
    cudaGetSymbolAddress((void**)&p_y4,  g_y4);

    cudaFuncSetAttribute(mlp_kernel, cudaFuncAttributeMaxDynamicSharedMemorySize, MLP_SMEM);

    prep_kernel<<<(NP + 255) / 256, 256>>>(pts);
    knn_kernel<<<NP, 256>>>();
    featknn_kernel<<<NP, 64>>>();
    axes_kernel<<<1, 256>>>();
    fd_kernel<<<(NP + 255) / 256, 256>>>();
    mlp_kernel<<<NP, 128, MLP_SMEM>>>(gw0, gw1, gw2, gw3, gw4);

    // conv1 (64 <- 4) + BN + relu
    gemm_kernel<<<dim3(NP / 64, 1), 256>>>(c1w, p_fd, c1b, p_y1, 64, 4);
    bn_stats_kernel<<<64, 256>>>(p_y1, bn1g, bn1b);
    bn_apply_kernel<<<64 * NP / 256, 256>>>(p_y1, p_y1);
    // conv2 (128 <- 64) + BN + relu -> concat rows 64..191
    gemm_kernel<<<dim3(NP / 64, 2), 256>>>(c2w, p_y1, c2b, p_y2, 128, 64);
    bn_stats_kernel<<<128, 256>>>(p_y2, bn2g, bn2b);
    bn_apply_kernel<<<128 * NP / 256, 256>>>(p_y2, p_emb + 64 * NP);
    // conv3 (256 <- 192) + BN + relu
    gemm_kernel<<<dim3(NP / 64, 4), 256>>>(c3w, p_emb, c3b, p_y3, 256, 192);
    bn_stats_kernel<<<256, 256>>>(p_y3, bn3g, bn3b);
    bn_apply_kernel<<<256 * NP / 256, 256>>>(p_y3, p_y3);
    // conv4 (1024 <- 256) + BN + relu -> out
    gemm_kernel<<<dim3(NP / 64, 16), 256>>>(c4w, p_y3, c4b, p_y4, 1024, 256);
    bn_stats_kernel<<<1024, 256>>>(p_y4, bn4g, bn4b);
    bn_apply_kernel<<<1024 * NP / 256, 256>>>(p_y4, out);

    (void)in_sizes; (void)n_in; (void)out_size;
}

// round 4
// speedup vs baseline: 1.1801x; 1.1801x over previous
#include <cuda_runtime.h>
#include <stdint.h>

#define NP   8192
#define KNN  64
#define EPSF 1e-7f
typedef unsigned long long ull;

// ------------------------- static scratch -------------------------
__device__ float g_px[NP], g_py[NP], g_pz[NP], g_vn[NP];
__device__ __align__(16) float4 g_pt4[NP];
__device__ ull   g_gmax, g_gmin;
__device__ int   g_idx[NP * KNN];
__device__ __align__(16) float g_feat[NP * KNN * 4];
__device__ __align__(16) float g_fd[NP * 4];
__device__ __align__(16) float g_emb[192 * NP];
__device__ __align__(16) float g_y1[64 * NP];
__device__ __align__(16) float g_y2[128 * NP];
__device__ __align__(16) float g_y3[256 * NP];
__device__ __align__(16) float g_y4[1024 * NP];
__device__ float g_sc[1024], g_sh[1024];

// ------------------------- f32x2 helpers -------------------------
__device__ __forceinline__ ull ffma2(ull a, ull b, ull c) {
    ull d;
    asm("fma.rn.f32x2 %0, %1, %2, %3;" : "=l"(d) : "l"(a), "l"(b), "l"(c));
    return d;
}
__device__ __forceinline__ ull pack2(float x, float y) {
    ull d;
    asm("mov.b64 %0, {%1, %2};" : "=l"(d) : "f"(x), "f"(y));
    return d;
}
__device__ __forceinline__ void unpack2(ull v, float& x, float& y) {
    asm("mov.b64 {%0, %1}, %2;" : "=f"(x), "=f"(y) : "l"(v));
}

// ------------------------- prep -------------------------
__global__ void prep_kernel(const float* __restrict__ pts) {
    int i = blockIdx.x * blockDim.x + threadIdx.x;
    if (i == 0) { g_gmax = 0ULL; g_gmin = ~0ULL; }
    if (i < NP) {
        float x = pts[3 * i], y = pts[3 * i + 1], z = pts[3 * i + 2];
        g_px[i] = x; g_py[i] = y; g_pz[i] = z;
        float rr = x * x + y * y + z * z;
        g_vn[i] = sqrtf(rr);
        g_pt4[i] = make_float4(x, y, z, rr);
    }
}

// ------------------------- KNN rank-64 selection -------------------------
__global__ void __launch_bounds__(256) knn_kernel() {
    const int i = blockIdx.x, tid = threadIdx.x;
    const int lane = tid & 31, warp = tid >> 5;
    __shared__ int wsum[16];
    __shared__ ull cmin;
    __shared__ int nless, neq, nact;
    __shared__ int eqbuf[256];
    __shared__ unsigned short actkey[2048];

    float4 q4 = g_pt4[i];
    unsigned key[32];
#pragma unroll
    for (int s = 0; s < 32; s++) {
        float4 p = g_pt4[s * 256 + tid];
        float d = q4.w - 2.0f * (q4.x * p.x + q4.y * p.y + q4.z * p.z) + p.w;
        unsigned u = __float_as_uint(d);
        key[s] = u ^ ((u & 0x80000000u) ? 0xFFFFFFFFu : 0x80000000u);
    }
    if (tid == 0) { cmin = ~0ULL; nless = 0; neq = 0; nact = 0; }
    __syncthreads();

    unsigned v = 0u;
    int cless = 0;
    // stage 1: bits 31..16 over register keys, one barrier/round (parity banks)
    for (int b = 31; b >= 16; b--) {
        unsigned cand = v | (1u << b);
        int cnt = 0;
#pragma unroll
        for (int s = 0; s < 32; s++) cnt += (key[s] < cand) ? 1 : 0;
        cnt = __reduce_add_sync(0xFFFFFFFFu, cnt);
        int bank = (b & 1) << 3;
        if (lane == 0) wsum[bank + warp] = cnt;
        __syncthreads();
        int tot = 0;
#pragma unroll
        for (int w = 0; w < 8; w++) tot += wsum[bank + w];
        if (tot < KNN) { v = cand; cless = tot; }
    }

    // compact candidates with matching high-16 prefix
    unsigned p16 = v >> 16;
#pragma unroll
    for (int s = 0; s < 32; s++) {
        if ((key[s] >> 16) == p16) {
            int a = atomicAdd(&nact, 1);
            if (a < 2048) actkey[a] = (unsigned short)(key[s] & 0xFFFFu);
        }
    }
    __syncthreads();
    int na = nact;
    int base = cless;  // count of keys with key < (p16<<16)

    if (na <= 2048) {
        for (int b = 15; b >= 0; b--) {
            unsigned cl = (v | (1u << b)) & 0xFFFFu;
            int cnt = 0;
            for (int t = tid; t < na; t += 256) cnt += (actkey[t] < cl) ? 1 : 0;
            cnt = __reduce_add_sync(0xFFFFFFFFu, cnt);
            int bank = (b & 1) << 3;
            if (lane == 0) wsum[bank + warp] = cnt;
            __syncthreads();
            int tot = base;
#pragma unroll
            for (int w = 0; w < 8; w++) tot += wsum[bank + w];
            if (tot < KNN) { v |= (1u << b); cless = tot; }
        }
    } else {
        // fallback: full register rounds on low bits
        for (int b = 15; b >= 0; b--) {
            unsigned cand = v | (1u << b);
            int cnt = 0;
#pragma unroll
            for (int s = 0; s < 32; s++) cnt += (key[s] < cand) ? 1 : 0;
            cnt = __reduce_add_sync(0xFFFFFFFFu, cnt);
            int bank = (b & 1) << 3;
            if (lane == 0) wsum[bank + warp] = cnt;
            __syncthreads();
            int tot = 0;
#pragma unroll
            for (int w = 0; w < 8; w++) tot += wsum[bank + w];
            if (tot < KNN) { v = cand; cless = tot; }
        }
    }

    // center = lexicographic min (key, index)
    ull lm = ~0ULL;
#pragma unroll
    for (int s = 0; s < 32; s++) {
        ull pk = (((ull)key[s]) << 32) | (unsigned)(s * 256 + tid);
        lm = (pk < lm) ? pk : lm;
    }
    atomicMin(&cmin, lm);
    __syncthreads();
    int center = (int)(cmin & 0xFFFFFFFFu);
    unsigned ckey = (unsigned)(cmin >> 32);
    int startEq = (ckey == v) ? (cless + 1) : cless;

#pragma unroll
    for (int s = 0; s < 32; s++) {
        int n = s * 256 + tid;
        unsigned kk = key[s];
        if (n == center) continue;
        if (kk < v) {
            int p = atomicAdd(&nless, 1);
            g_idx[i * KNN + 1 + p] = n;
        } else if (kk == v) {
            int e = atomicAdd(&neq, 1);
            if (e < 256) eqbuf[e] = n;
        }
    }
    __syncthreads();
    if (tid == 0) {
        g_idx[i * KNN] = center;
        int q = KNN - startEq;               // equals to take, smallest indices first
        int m = neq; if (m > 256) m = 256;
        for (int a = 0; a < q; a++) {
            int bi = a;
            for (int bj = a + 1; bj < m; bj++)
                if (eqbuf[bj] < eqbuf[bi]) bi = bj;
            int t = eqbuf[a]; eqbuf[a] = eqbuf[bi]; eqbuf[bi] = t;
            g_idx[i * KNN + startEq + a] = eqbuf[a];
        }
    }
}

// ------------------ per-query rotation-invariant KNN features ------------------
__global__ void __launch_bounds__(64) featknn_kernel() {
    int i = blockIdx.x, k = threadIdx.x;
    __shared__ int sidx[64];
    __shared__ float sx[64], sy[64], sz[64];
    __shared__ ull sred[64];
    __shared__ float rx[64], ry[64], rz[64];

    sidx[k] = g_idx[i * KNN + k];
    __syncthreads();
    // deterministic order: odd-even sort slots 1..63 by point index
    for (int ph = 0; ph < 63; ph++) {
        int a = 1 + (ph & 1) + 2 * k;
        if (a + 1 <= 63) {
            int u = sidx[a], w = sidx[a + 1];
            if (w < u) { sidx[a] = w; sidx[a + 1] = u; }
        }
        __syncthreads();
    }

    int j  = sidx[k];
    int c0 = sidx[0];
    float pcx = g_px[j] - g_px[c0];
    float pcy = g_py[j] - g_py[c0];
    float pcz = g_pz[j] - g_pz[c0];
    float vn  = sqrtf(pcx * pcx + pcy * pcy + pcz * pcz);
    sx[k] = pcx; sy[k] = pcy; sz[k] = pcz;
    rx[k] = pcx; ry[k] = pcy; rz[k] = pcz;
    sred[k] = (((ull)__float_as_uint(vn)) << 32) | (unsigned)(63 - k);
    __syncthreads();
    for (int off = 32; off > 0; off >>= 1) {
        if (k < off) {
            rx[k] += rx[k + off]; ry[k] += ry[k + off]; rz[k] += rz[k + off];
            ull o = sred[k + off];
            if (o > sred[k]) sred[k] = o;
        }
        __syncthreads();
    }
    int id1 = 63 - (int)(sred[0] & 0xFFFFFFFFu);
    float a1x = sx[id1], a1y = sy[id1], a1z = sz[id1];
    float n1 = sqrtf(a1x * a1x + a1y * a1y + a1z * a1z) + EPSF;
    a1x /= n1; a1y /= n1; a1z /= n1;
    float a2x = rx[0] * (1.0f / 64.0f), a2y = ry[0] * (1.0f / 64.0f), a2z = rz[0] * (1.0f / 64.0f);
    float n2 = sqrtf(a2x * a2x + a2y * a2y + a2z * a2z) + EPSF;
    a2x /= n2; a2y /= n2; a2z /= n2;
    float a3x = a1x + 1.5f * a2x, a3y = a1y + 1.5f * a2y, a3z = a1z + 1.5f * a2z;
    float n3 = sqrtf(a3x * a3x + a3y * a3y + a3z * a3z) + EPSF;
    a3x /= n3; a3y /= n3; a3z /= n3;

    float den = vn + EPSF;
    float f1 = (pcx * a1x + pcy * a1y + pcz * a1z) / den;
    float f2 = (pcx * a2x + pcy * a2y + pcz * a2z) / den;
    float f3 = (pcx * a3x + pcy * a3y + pcz * a3z) / den;
    *(float4*)(g_feat + (size_t)(i * KNN + k) * 4) = make_float4(f1, f2, f3, vn);
}

// ------------------ global axes reduce ------------------
__global__ void __launch_bounds__(256) axes_reduce_kernel() {
    int t = blockIdx.x * blockDim.x + threadIdx.x;
    int lane = threadIdx.x & 31;
    unsigned b = __float_as_uint(g_vn[t]);   // vn >= 0: uint order == float order
    ull pmx = (((ull)b) << 32) | (unsigned)(0xFFFFFFFFu - t);
    ull pmn = (((ull)b) << 32) | (unsigned)t;
#pragma unroll
    for (int off = 16; off > 0; off >>= 1) {
        ull ox = __shfl_down_sync(0xFFFFFFFFu, pmx, off);
        ull on = __shfl_down_sync(0xFFFFFFFFu, pmn, off);
        if (ox > pmx) pmx = ox;
        if (on < pmn) pmn = on;
    }
    if (lane == 0) { atomicMax(&g_gmax, pmx); atomicMin(&g_gmin, pmn); }
}

__global__ void fd_kernel() {
    int i = blockIdx.x * blockDim.x + threadIdx.x;
    if (i >= NP) return;
    int i1 = (int)(0xFFFFFFFFu - (unsigned)(g_gmax & 0xFFFFFFFFu));
    int i2 = (int)(g_gmin & 0xFFFFFFFFu);
    float n1 = g_vn[i1] + EPSF;
    float a1x = g_px[i1] / n1, a1y = g_py[i1] / n1, a1z = g_pz[i1] / n1;
    float n2 = g_vn[i2] + EPSF;
    float a2x = g_px[i2] / n2, a2y = g_py[i2] / n2, a2z = g_pz[i2] / n2;
    float a3x = a1x + 1.5f * a2x, a3y = a1y + 1.5f * a2y, a3z = a1z + 1.5f * a2z;
    float n3 = sqrtf(a3x * a3x + a3y * a3y + a3z * a3z) + EPSF;
    a3x /= n3; a3y /= n3; a3z /= n3;
    float x = g_px[i], y = g_py[i], z = g_pz[i], vn = g_vn[i];
    float den = vn + EPSF;
    float f1 = (x * a1x + y * a1y + z * a1z) / den;
    float f2 = (x * a2x + y * a2y + z * a2z) / den;
    float f3 = (x * a3x + y * a3y + z * a3z) / den;
    *(float4*)(g_fd + (size_t)i * 4) = make_float4(f1, f2, f3, vn);
}

// ------------------ fused 5-layer MLP + max over K (2 points/block) ------------------
#define MLP_W_FLOATS 16640
#define MLP_SMEM ((MLP_W_FLOATS + 4 * 64 * 66) * 4)
__global__ void __launch_bounds__(256) mlp_kernel(const float* __restrict__ gw0,
                                                  const float* __restrict__ gw1,
                                                  const float* __restrict__ gw2,
                                                  const float* __restrict__ gw3,
                                                  const float* __restrict__ gw4) {
    extern __shared__ float smem[];
    float* w = smem;
    int tid = threadIdx.x;
    int half = tid >> 7, t128 = tid & 127;
    float* A = smem + MLP_W_FLOATS + half * (2 * 4224);
    float* B = A + 4224;
    int i = blockIdx.x * 2 + half;

    float4* wf = (float4*)w;
    for (int t = tid; t < 64; t += 256) wf[t] = ((const float4*)gw0)[t];
    {
        const float* gws[4] = {gw1, gw2, gw3, gw4};
        for (int l = 0; l < 4; l++)
            for (int t = tid; t < 1024; t += 256) wf[64 + l * 1024 + t] = ((const float4*)gws[l])[t];
    }
    for (int r = t128; r < 64; r += 128) {
        float4 f = *(const float4*)(g_feat + (size_t)(i * 64 + r) * 4);
        A[r * 66 + 0] = f.x; A[r * 66 + 1] = f.y; A[r * 66 + 2] = f.z; A[r * 66 + 3] = f.w;
    }
    __syncthreads();

    int r = t128 >> 1, h = t128 & 1;
    float* cur = A; float* nxt = B;
    const float* wl = w; int Kc = 4;
    for (int layer = 0; layer < 5; layer++) {
        ull acc[16];
#pragma unroll
        for (int q = 0; q < 16; q++) acc[q] = 0ULL;
        const float* wj = wl + h * 32;
        for (int c = 0; c < Kc; c++) {
            float xv = cur[r * 66 + c];
            ull xx = pack2(xv, xv);
            const float4* wrow = (const float4*)(wj + c * 64);
#pragma unroll
            for (int q4 = 0; q4 < 8; q4++) {
                float4 wv = wrow[q4];
                acc[q4 * 2]     = ffma2(xx, pack2(wv.x, wv.y), acc[q4 * 2]);
                acc[q4 * 2 + 1] = ffma2(xx, pack2(wv.z, wv.w), acc[q4 * 2 + 1]);
            }
        }
        float* orow = nxt + r * 66 + h * 32;
#pragma unroll
        for (int q = 0; q < 16; q++) {
            float vx, vy; unpack2(acc[q], vx, vy);
            float2 o; o.x = fmaxf(vx, 0.f); o.y = fmaxf(vy, 0.f);
            *(float2*)(orow + q * 2) = o;
        }
        __syncthreads();
        float* t = cur; cur = nxt; nxt = t;
        wl = w + 256 + layer * 4096; Kc = 64;
    }
    if (t128 < 64) {
        float m = cur[t128];
        for (int r2 = 1; r2 < 64; r2++) m = fmaxf(m, cur[r2 * 66 + t128]);
        g_emb[i * 64 + t128] = m;   // flat [n][64] view == conv input [64][8192]
    }
}

// ------------------ GEMM: Y[M][8192] = W[M][Kc] @ X[Kc][8192] + bias ------------------
// tile M=64, N=128, 256 threads, 4m x 8n per thread via f32x2
__global__ void __launch_bounds__(256) gemm_kernel(const float* __restrict__ W,
                                                   const float* __restrict__ X,
                                                   const float* __restrict__ bias,
                                                   float* __restrict__ Y,
                                                   int Kc) {
    __shared__ float sW[16][68];
    __shared__ float sX[16][132];
    int tid = threadIdx.x;
    int bm = blockIdx.y * 64, bn = blockIdx.x * 128;
    int tx = tid & 15, ty = tid >> 4;
    ull acc[4][4];
#pragma unroll
    for (int u = 0; u < 4; u++)
#pragma unroll
        for (int q = 0; q < 4; q++) acc[u][q] = 0ULL;

    for (int k0 = 0; k0 < Kc; k0 += 16) {
        for (int t = tid; t < 1024; t += 256) {
            int kk = t & 15, m = t >> 4;
            float val = 0.f;
            if (k0 + kk < Kc) val = W[(size_t)(bm + m) * Kc + k0 + kk];
            sW[kk][m] = val;
        }
        for (int t = tid; t < 2048; t += 256) {
            int n = t & 127, kk = t >> 7;
            float val = 0.f;
            if (k0 + kk < Kc) val = X[(size_t)(k0 + kk) * NP + bn + n];
            sX[kk][n] = val;
        }
        __syncthreads();
#pragma unroll
        for (int kk = 0; kk < 16; kk++) {
            float4 a  = *(const float4*)&sW[kk][ty * 4];
            float4 b0 = *(const float4*)&sX[kk][tx * 8];
            float4 b1 = *(const float4*)&sX[kk][tx * 8 + 4];
            ull bp0 = pack2(b0.x, b0.y), bp1 = pack2(b0.z, b0.w);
            ull bp2 = pack2(b1.x, b1.y), bp3 = pack2(b1.z, b1.w);
            float av[4] = {a.x, a.y, a.z, a.w};
#pragma unroll
            for (int u = 0; u < 4; u++) {
                ull aa = pack2(av[u], av[u]);
                acc[u][0] = ffma2(aa, bp0, acc[u][0]);
                acc[u][1] = ffma2(aa, bp1, acc[u][1]);
                acc[u][2] = ffma2(aa, bp2, acc[u][2]);
                acc[u][3] = ffma2(aa, bp3, acc[u][3]);
            }
        }
        __syncthreads();
    }
    int m0 = bm + ty * 4;
#pragma unroll
    for (int u = 0; u < 4; u++) {
        float bv = bias[m0 + u];
        float o[8];
#pragma unroll
        for (int q = 0; q < 4; q++) {
            float vx, vy; unpack2(acc[u][q], vx, vy);
            o[q * 2] = vx + bv; o[q * 2 + 1] = vy + bv;
        }
        float* yrow = Y + (size_t)(m0 + u) * NP + bn + tx * 8;
        *(float4*)yrow       = make_float4(o[0], o[1], o[2], o[3]);
        *(float4*)(yrow + 4) = make_float4(o[4], o[5], o[6], o[7]);
    }
}

// ------------------ BatchNorm (training stats, one pass) ------------------
__global__ void __launch_bounds__(256) bn_stats_kernel(const float* __restrict__ Y,
                                                       const float* __restrict__ gamma,
                                                       const float* __restrict__ beta) {
    int ch = blockIdx.x, tid = threadIdx.x;
    const float4* row = (const float4*)(Y + (size_t)ch * NP);
    float s = 0.f, s2 = 0.f;
    for (int t = tid; t < NP / 4; t += 256) {
        float4 v = row[t];
        s  += v.x + v.y + v.z + v.w;
        s2 += v.x * v.x + v.y * v.y + v.z * v.z + v.w * v.w;
    }
    __shared__ float r1[256], r2[256];
    r1[tid] = s; r2[tid] = s2; __syncthreads();
    for (int off = 128; off > 0; off >>= 1) {
        if (tid < off) { r1[tid] += r1[tid + off]; r2[tid] += r2[tid + off]; }
        __syncthreads();
    }
    if (tid == 0) {
        float mu = r1[0] * (1.0f / NP);
        float var = r2[0] * (1.0f / NP) - mu * mu;
        var = fmaxf(var, 0.f);
        float sc = gamma[ch] * rsqrtf(var + 1e-5f);
        g_sc[ch] = sc;
        g_sh[ch] = beta[ch] - mu * sc;
    }
}

__global__ void bn_apply_kernel(const float4* __restrict__ Yin, float4* __restrict__ Yout) {
    int idx = blockIdx.x * blockDim.x + threadIdx.x;  // over M*NP/4
    int ch = idx >> 11;                               // NP/4 = 2048 per channel
    float sc = g_sc[ch], sh = g_sh[ch];
    float4 v = Yin[idx];
    v.x = fmaxf(v.x * sc + sh, 0.f);
    v.y = fmaxf(v.y * sc + sh, 0.f);
    v.z = fmaxf(v.z * sc + sh, 0.f);
    v.w = fmaxf(v.w * sc + sh, 0.f);
    Yout[idx] = v;
}

// ------------------------- launch -------------------------
extern "C" void kernel_launch(void* const* d_in, const int* in_sizes, int n_in,
                              void* d_out, int out_size) {
    const float* pts  = (const float*)d_in[0];
    const float* gw0  = (const float*)d_in[1];
    const float* gw1  = (const float*)d_in[2];
    const float* gw2  = (const float*)d_in[3];
    const float* gw3  = (const float*)d_in[4];
    const float* gw4  = (const float*)d_in[5];
    const float* c1w  = (const float*)d_in[6];
    const float* c1b  = (const float*)d_in[7];
    const float* bn1g = (const float*)d_in[8];
    const float* bn1b = (const float*)d_in[9];
    const float* c2w  = (const float*)d_in[10];
    const float* c2b  = (const float*)d_in[11];
    const float* bn2g = (const float*)d_in[12];
    const float* bn2b = (const float*)d_in[13];
    const float* c3w  = (const float*)d_in[14];
    const float* c3b  = (const float*)d_in[15];
    const float* bn3g = (const float*)d_in[16];
    const float* bn3b = (const float*)d_in[17];
    const float* c4w  = (const float*)d_in[18];
    const float* c4b  = (const float*)d_in[19];
    const float* bn4g = (const float*)d_in[20];
    const float* bn4b = (const float*)d_in[21];
    float* out = (float*)d_out;

    float *p_fd, *p_emb, *p_y1, *p_y2, *p_y3, *p_y4;
    cudaGetSymbolAddress((void**)&p_fd,  g_fd);
    cudaGetSymbolAddress((void**)&p_emb, g_emb);
    cudaGetSymbolAddress((void**)&p_y1,  g_y1);
    cudaGetSymbolAddress((void**)&p_y2,  g_y2);
    cudaGetSymbolAddress((void**)&p_y3,  g_y3);
    cudaGetSymbolAddress((void**)&p_y4,  g_y4);

    cudaFuncSetAttribute(mlp_kernel, cudaFuncAttributeMaxDynamicSharedMemorySize, MLP_SMEM);

    prep_kernel<<<(NP + 255) / 256, 256>>>(pts);
    knn_kernel<<<NP, 256>>>();
    featknn_kernel<<<NP, 64>>>();
    axes_reduce_kernel<<<NP / 256, 256>>>();
    fd_kernel<<<(NP + 255) / 256, 256>>>();
    mlp_kernel<<<NP / 2, 256, MLP_SMEM>>>(gw0, gw1, gw2, gw3, gw4);

    // conv1 (64 <- 4) + BN + relu
    gemm_kernel<<<dim3(NP / 128, 1), 256>>>(c1w, p_fd, c1b, p_y1, 4);
    bn_stats_kernel<<<64, 256>>>(p_y1, bn1g, bn1b);
    bn_apply_kernel<<<64 * NP / 1024, 256>>>((const float4*)p_y1, (float4*)p_y1);
    // conv2 (128 <- 64) + BN + relu -> concat rows 64..191
    gemm_kernel<<<dim3(NP / 128, 2), 256>>>(c2w, p_y1, c2b, p_y2, 64);
    bn_stats_kernel<<<128, 256>>>(p_y2, bn2g, bn2b);
    bn_apply_kernel<<<128 * NP / 1024, 256>>>((const float4*)p_y2, (float4*)(p_emb + 64 * NP));
    // conv3 (256 <- 192) + BN + relu
    gemm_kernel<<<dim3(NP / 128, 4), 256>>>(c3w, p_emb, c3b, p_y3, 192);
    bn_stats_kernel<<<256, 256>>>(p_y3, bn3g, bn3b);
    bn_apply_kernel<<<256 * NP / 1024, 256>>>((const float4*)p_y3, (float4*)p_y3);
    // conv4 (1024 <- 256) + BN + relu -> out
    gemm_kernel<<<dim3(NP / 128, 16), 256>>>(c4w, p_y3, c4b, p_y4, 256);
    bn_stats_kernel<<<1024, 256>>>(p_y4, bn4g, bn4b);
    bn_apply_kernel<<<1024 * NP / 1024, 256>>>((const float4*)p_y4, (float4*)out);

    (void)in_sizes; (void)n_in; (void)out_size;
}